// round 8
// baseline (speedup 1.0000x reference)
#include <cuda_runtime.h>
#include <cuda_bf16.h>

// high_order_residual (braq, order=2), row-wise over (11008, 4096).
// One CTA per row, 256 threads x 16 elements, single HBM pass.
// Mask arrives as int32 words (nonzero = true).
//
// R8: 3 block reductions (mean1 via closed form from sign counts),
//     mask + centered0 signs kept as bit-words instead of float arrays
//     to cut register pressure and raise occupancy.

#define ROW_LEN 4096
#define NTHREADS 256
#define CHUNKS 4          // float4/int4 chunks per thread (4*4 = 16 elems)

// Two-value block reduction. sb must be >= 18 floats, unique per call site.
__device__ __forceinline__ void block_reduce2(float& a, float& b, float* sb) {
#pragma unroll
    for (int o = 16; o > 0; o >>= 1) {
        a += __shfl_down_sync(0xFFFFFFFFu, a, o);
        b += __shfl_down_sync(0xFFFFFFFFu, b, o);
    }
    const int w = threadIdx.x >> 5;
    if ((threadIdx.x & 31) == 0) { sb[w] = a; sb[8 + w] = b; }
    __syncthreads();
    if (threadIdx.x == 0) {
        float ra = sb[0], rb = sb[8];
#pragma unroll
        for (int i = 1; i < 8; i++) { ra += sb[i]; rb += sb[8 + i]; }
        sb[16] = ra; sb[17] = rb;
    }
    __syncthreads();
    a = sb[16];
    b = sb[17];
}

// One-value block reduction.
__device__ __forceinline__ void block_reduce1(float& a, float* sb) {
#pragma unroll
    for (int o = 16; o > 0; o >>= 1)
        a += __shfl_down_sync(0xFFFFFFFFu, a, o);
    const int w = threadIdx.x >> 5;
    if ((threadIdx.x & 31) == 0) sb[w] = a;
    __syncthreads();
    if (threadIdx.x == 0) {
        float ra = sb[0];
#pragma unroll
        for (int i = 1; i < 8; i++) ra += sb[i];
        sb[16] = ra;
    }
    __syncthreads();
    a = sb[16];
}

__global__ __launch_bounds__(NTHREADS) void braq_order2_kernel(
    const float* __restrict__ x,
    const int* __restrict__ mask,
    float* __restrict__ out)
{
    __shared__ float sred[3][18];

    const int row = blockIdx.x;
    const int tid = threadIdx.x;
    const size_t base = (size_t)row * ROW_LEN;

    const float4* __restrict__ xp = reinterpret_cast<const float4*>(x + base);
    const int4*   __restrict__ mp = reinterpret_cast<const int4*>(mask + base);

    float v[16];              // xm -> centered1
    unsigned int mbits = 0;   // per-element mask bits
    unsigned int pbits = 0;   // centered0 > 0
    unsigned int nbits = 0;   // centered0 < 0

    // ---- Load + first-pass stats: cnt, sum(xm) ----
    float cnt = 0.0f, s0 = 0.0f;
#pragma unroll
    for (int k = 0; k < CHUNKS; k++) {
        const int idx = tid + k * NTHREADS;
        const float4 xv = xp[idx];
        const int4 mw = mp[idx];
        const unsigned int b0 = (mw.x != 0);
        const unsigned int b1 = (mw.y != 0);
        const unsigned int b2 = (mw.z != 0);
        const unsigned int b3 = (mw.w != 0);
        mbits |= (b0 << (k * 4 + 0)) | (b1 << (k * 4 + 1)) |
                 (b2 << (k * 4 + 2)) | (b3 << (k * 4 + 3));
        v[k * 4 + 0] = b0 ? xv.x : 0.0f;
        v[k * 4 + 1] = b1 ? xv.y : 0.0f;
        v[k * 4 + 2] = b2 ? xv.z : 0.0f;
        v[k * 4 + 3] = b3 ? xv.w : 0.0f;
        cnt += (float)(b0 + b1 + b2 + b3);
        s0 += v[k * 4 + 0] + v[k * 4 + 1] + v[k * 4 + 2] + v[k * 4 + 3];
    }

    block_reduce2(cnt, s0, sred[0]);
    const float inv_cnt = 1.0f / fmaxf(cnt, 1.0f);
    const float mean0 = s0 * inv_cnt;   // 0 when cnt==0 (s0==0 too)

    // ---- Iteration 0: centered0, reduce (sum|c0|, sign-count diff) ----
    float a0 = 0.0f;
#pragma unroll
    for (int i = 0; i < 16; i++) {
        const bool mi = (mbits >> i) & 1u;
        const float c = mi ? (v[i] - mean0) : 0.0f;
        pbits |= ((unsigned int)(c > 0.0f)) << i;
        nbits |= ((unsigned int)(c < 0.0f)) << i;
        a0 += fabsf(c);
    }
    float d0 = (float)(__popc(pbits) - __popc(nbits));
    block_reduce2(a0, d0, sred[1]);
    const float scale0 = a0 * inv_cnt;

    // mean1 in closed form:
    //   sum(residual1) = s0 - sum(binary0*m)
    //   sum(binary0*m) = scale0 * (P0 - N0) + cnt * mean0
    const float sum_b0 = scale0 * d0 + cnt * mean0;
    const float mean1 = (s0 - sum_b0) * inv_cnt;

    // ---- Iteration 1: centered1, reduce sum|c1| ----
    float a1 = 0.0f;
#pragma unroll
    for (int i = 0; i < 16; i++) {
        const bool mi = (mbits >> i) & 1u;
        const float sg0 = ((pbits >> i) & 1u) ? 1.0f
                        : (((nbits >> i) & 1u) ? -1.0f : 0.0f);
        const float b0m = mi ? fmaf(sg0, scale0, mean0) : 0.0f;
        const float c1 = mi ? (v[i] - b0m - mean1) : 0.0f;
        v[i] = c1;
        a1 += fabsf(c1);
    }
    block_reduce1(a1, sred[2]);
    const float scale1 = a1 * inv_cnt;

    // ---- binary0 + binary1, store ----
    float4* __restrict__ op = reinterpret_cast<float4*>(out + base);
#pragma unroll
    for (int k = 0; k < CHUNKS; k++) {
        const int idx = tid + k * NTHREADS;
        float4 o;
        float* oc = &o.x;
#pragma unroll
        for (int j = 0; j < 4; j++) {
            const int i = k * 4 + j;
            const bool mi = (mbits >> i) & 1u;
            const float sg0 = ((pbits >> i) & 1u) ? 1.0f
                            : (((nbits >> i) & 1u) ? -1.0f : 0.0f);
            const float c1 = v[i];
            const float sg1 = (float)((c1 > 0.0f) - (c1 < 0.0f));
            const float b0 = fmaf(sg0, scale0, mean0);
            const float b1 = fmaf(sg1, scale1, mean1);
            oc[j] = mi ? (b0 + b1) : 0.0f;
        }
        op[idx] = o;
    }
}

extern "C" void kernel_launch(void* const* d_in, const int* in_sizes, int n_in,
                              void* d_out, int out_size) {
    const float* x = (const float*)d_in[0];
    const int* mask = (const int*)d_in[1];
    float* out = (float*)d_out;

    const int rows = in_sizes[0] / ROW_LEN;   // 11008
    braq_order2_kernel<<<rows, NTHREADS>>>(x, mask, out);
}

// round 9
// speedup vs baseline: 1.1470x; 1.1470x over previous
#include <cuda_runtime.h>
#include <cuda_bf16.h>

// high_order_residual (braq, order=2), row-wise over (11008, 4096).
// One CTA per row, 256 threads x 16 elements, single HBM pass.
// Mask arrives as int32 words (nonzero = true).
//
// R9: float-based layout (R7), closed-form mean1 (3 reductions instead of 4),
//     single-barrier reductions (leaders write partials, everyone sums via
//     broadcast LDS) -> 3 __syncthreads per row instead of 8.

#define ROW_LEN 4096
#define NTHREADS 256
#define CHUNKS 4          // float4/int4 chunks per thread (4*4 = 16 elems)

// Two-value block reduction, ONE __syncthreads. sb >= 16 floats, unique
// per call site. All threads end with the identical (deterministic) sums.
__device__ __forceinline__ void block_reduce2(float& a, float& b, float* sb) {
#pragma unroll
    for (int o = 16; o > 0; o >>= 1) {
        a += __shfl_down_sync(0xFFFFFFFFu, a, o);
        b += __shfl_down_sync(0xFFFFFFFFu, b, o);
    }
    const int w = threadIdx.x >> 5;
    if ((threadIdx.x & 31) == 0) { sb[2 * w] = a; sb[2 * w + 1] = b; }
    __syncthreads();
    float ra = sb[0], rb = sb[1];
#pragma unroll
    for (int i = 1; i < 8; i++) { ra += sb[2 * i]; rb += sb[2 * i + 1]; }
    a = ra;
    b = rb;
}

// One-value block reduction, ONE __syncthreads.
__device__ __forceinline__ void block_reduce1(float& a, float* sb) {
#pragma unroll
    for (int o = 16; o > 0; o >>= 1)
        a += __shfl_down_sync(0xFFFFFFFFu, a, o);
    const int w = threadIdx.x >> 5;
    if ((threadIdx.x & 31) == 0) sb[w] = a;
    __syncthreads();
    float ra = sb[0];
#pragma unroll
    for (int i = 1; i < 8; i++) ra += sb[i];
    a = ra;
}

__global__ __launch_bounds__(NTHREADS) void braq_order2_kernel(
    const float* __restrict__ x,
    const int* __restrict__ mask,
    float* __restrict__ out)
{
    __shared__ float sred0[16];
    __shared__ float sred1[16];
    __shared__ float sred2[8];

    const int row = blockIdx.x;
    const int tid = threadIdx.x;
    const size_t base = (size_t)row * ROW_LEN;

    const float4* __restrict__ xp = reinterpret_cast<const float4*>(x + base);
    const int4*   __restrict__ mp = reinterpret_cast<const int4*>(mask + base);

    float v[16];    // xm -> centered1
    float acc[16];  // centered0 -> binary0*m
    float mf[16];   // mask as 0/1 float

    // ---- Load + first-pass stats: cnt, sum(xm) ----
    float cnt = 0.0f, s0 = 0.0f;
#pragma unroll
    for (int k = 0; k < CHUNKS; k++) {
        const int idx = tid + k * NTHREADS;
        const float4 xv = xp[idx];
        const int4 mw = mp[idx];
        const float m0 = mw.x ? 1.0f : 0.0f;
        const float m1 = mw.y ? 1.0f : 0.0f;
        const float m2 = mw.z ? 1.0f : 0.0f;
        const float m3 = mw.w ? 1.0f : 0.0f;
        mf[k * 4 + 0] = m0;
        mf[k * 4 + 1] = m1;
        mf[k * 4 + 2] = m2;
        mf[k * 4 + 3] = m3;
        v[k * 4 + 0] = xv.x * m0;
        v[k * 4 + 1] = xv.y * m1;
        v[k * 4 + 2] = xv.z * m2;
        v[k * 4 + 3] = xv.w * m3;
        cnt += m0 + m1 + m2 + m3;
        s0 += v[k * 4 + 0] + v[k * 4 + 1] + v[k * 4 + 2] + v[k * 4 + 3];
    }

    block_reduce2(cnt, s0, sred0);
    const float inv_cnt = 1.0f / fmaxf(cnt, 1.0f);
    const float mean0 = s0 * inv_cnt;   // 0 when cnt==0 (s0==0 too)

    // ---- Iteration 0: centered0; reduce (sum|c0|, sum sign(c0)) ----
    float a0 = 0.0f, d0 = 0.0f;
#pragma unroll
    for (int i = 0; i < 16; i++) {
        const float c = (v[i] - mean0) * mf[i];
        acc[i] = c;                      // stash centered0
        a0 += fabsf(c);
        d0 += (float)((c > 0.0f) - (c < 0.0f));
    }
    block_reduce2(a0, d0, sred1);
    const float scale0 = a0 * inv_cnt;

    // Closed-form mean1:
    //   sum(residual1) = s0 - sum(binary0*m)
    //   sum(binary0*m) = scale0 * d0 + cnt * mean0
    const float sum_b0 = scale0 * d0 + cnt * mean0;
    const float mean1 = (s0 - sum_b0) * inv_cnt;

    // ---- binary0, residual1, centered1; reduce sum|c1| ----
    float a1 = 0.0f;
#pragma unroll
    for (int i = 0; i < 16; i++) {
        const float c = acc[i];
        const float sg = (float)((c > 0.0f) - (c < 0.0f));
        const float b0m = fmaf(sg, scale0, mean0) * mf[i];
        acc[i] = b0m;                    // binary0 * m (partial output)
        const float c1 = (v[i] - b0m - mean1) * mf[i];
        v[i] = c1;                       // stash centered1
        a1 += fabsf(c1);
    }
    block_reduce1(a1, sred2);
    const float scale1 = a1 * inv_cnt;

    // ---- binary1 + store ----
    float4* __restrict__ op = reinterpret_cast<float4*>(out + base);
#pragma unroll
    for (int k = 0; k < CHUNKS; k++) {
        const int idx = tid + k * NTHREADS;
        float4 o;
        float* oc = &o.x;
#pragma unroll
        for (int j = 0; j < 4; j++) {
            const int i = k * 4 + j;
            const float c1 = v[i];
            const float sg1 = (float)((c1 > 0.0f) - (c1 < 0.0f));
            oc[j] = acc[i] + fmaf(sg1, scale1, mean1) * mf[i];
        }
        op[idx] = o;
    }
}

extern "C" void kernel_launch(void* const* d_in, const int* in_sizes, int n_in,
                              void* d_out, int out_size) {
    const float* x = (const float*)d_in[0];
    const int* mask = (const int*)d_in[1];
    float* out = (float*)d_out;

    const int rows = in_sizes[0] / ROW_LEN;   // 11008
    braq_order2_kernel<<<rows, NTHREADS>>>(x, mask, out);
}